// round 17
// baseline (speedup 1.0000x reference)
#include <cuda_runtime.h>
#include <cuda_bf16.h>
#include <cstdint>
#include <cstddef>

// Problem dims
#define TT 512
#define BB 64
#define HH 1024
#define NG 4096              // 4*H, gate-interleaved: m (= n') = 4*j + gate(f,i,g,o)
#define KK 1024
#define KK2 2048             // stored K: [hi | lo]
#define BH (BB*HH)
#define BG (BB*NG)

typedef __nv_bfloat16 bf16;

// -------- device scratch (no allocations allowed) --------
__device__ __align__(16) bf16 g_Wx2[(size_t)NG * KK2]; // [m][hi|lo] for xproj
__device__ __align__(16) bf16 g_Wh2[(size_t)NG * KK2]; // [m][hi|lo] for recurrence
__device__ __align__(16) bf16 g_X2[(size_t)TT * BB * KK2]; // [s][hi|lo]
__device__ __align__(16) bf16 g_h2[2][BB * KK2];       // double-buffered h splits [b][hi|lo]
__device__ float g_ball[NG];
__device__ float g_XW[(size_t)TT * BB * NG];
__device__ unsigned int g_pf[TT * 128];                // produce flags: [t][group*8], 16 groups

// ---------------- low-level helpers (sm_80+ only) ----------------
__device__ __forceinline__ uint32_t smem_u32(const void* p) {
    uint32_t a;
    asm("{ .reg .u64 t; cvta.to.shared.u64 t, %1; cvt.u32.u64 %0, t; }" : "=r"(a) : "l"(p));
    return a;
}
__device__ __forceinline__ void cp16(uint32_t dst, const void* src) {
    asm volatile("cp.async.cg.shared.global [%0], [%1], 16;" :: "r"(dst), "l"(src) : "memory");
}
#define CP_COMMIT() asm volatile("cp.async.commit_group;" ::: "memory")
#define CP_WAIT1()  asm volatile("cp.async.wait_group 1;" ::: "memory")
#define CP_WAIT0()  asm volatile("cp.async.wait_group 0;" ::: "memory")

__device__ __forceinline__ float lds_f32(uint32_t a) {
    float v; asm volatile("ld.shared.f32 %0, [%1];" : "=f"(v) : "r"(a)); return v;
}
__device__ __forceinline__ void sts128(uint32_t a, uint4 v) {
    asm volatile("st.shared.v4.b32 [%0], {%1,%2,%3,%4};" :: "r"(a), "r"(v.x), "r"(v.y), "r"(v.z), "r"(v.w) : "memory");
}
__device__ __forceinline__ void sts_f32(uint32_t a, float v) {
    asm volatile("st.shared.f32 [%0], %1;" :: "r"(a), "f"(v) : "memory");
}
__device__ __forceinline__ void ldm4(uint32_t* r, uint32_t a) {
    asm volatile("ldmatrix.sync.aligned.m8n8.x4.shared.b16 {%0,%1,%2,%3}, [%4];"
        : "=r"(r[0]), "=r"(r[1]), "=r"(r[2]), "=r"(r[3]) : "r"(a));
}
__device__ __forceinline__ void mma16816(float* c,
                                         uint32_t a0, uint32_t a1, uint32_t a2, uint32_t a3,
                                         uint32_t b0, uint32_t b1) {
    asm volatile(
        "mma.sync.aligned.m16n8k16.row.col.f32.bf16.bf16.f32 "
        "{%0,%1,%2,%3}, {%4,%5,%6,%7}, {%8,%9}, {%0,%1,%2,%3};"
        : "+f"(c[0]), "+f"(c[1]), "+f"(c[2]), "+f"(c[3])
        : "r"(a0), "r"(a1), "r"(a2), "r"(a3), "r"(b0), "r"(b1));
}

// ---------------- prep kernels ----------------
// K-MAJOR index convention (idx = k*NG + n) — bias guard `idx < NG` valid only here.
__global__ void repack_kernel(const float* __restrict__ Wf, const float* __restrict__ Wi,
                              const float* __restrict__ Wg, const float* __restrict__ Wo,
                              const float* __restrict__ bf_, const float* __restrict__ bi_,
                              const float* __restrict__ bg_, const float* __restrict__ bo_) {
    int idx = blockIdx.x * 256 + threadIdx.x;   // idx = k*NG + n
    int k = idx >> 12;
    int n = idx & (NG - 1);
    int c = n >> 2, g = n & 3;
    const float* W = (g == 0) ? Wf : (g == 1) ? Wi : (g == 2) ? Wg : Wo;
    float wx = W[(size_t)k * HH + c];
    float wh = W[(size_t)(k + 1024) * HH + c];
    bf16 xh = __float2bfloat16(wx);
    g_Wx2[(size_t)n * KK2 + k]        = xh;
    g_Wx2[(size_t)n * KK2 + 1024 + k] = __float2bfloat16(wx - __bfloat162float(xh));
    bf16 hh = __float2bfloat16(wh);
    g_Wh2[(size_t)n * KK2 + k]        = hh;
    g_Wh2[(size_t)n * KK2 + 1024 + k] = __float2bfloat16(wh - __bfloat162float(hh));
    if (idx < NG) {
        const float* bv = (g == 0) ? bf_ : (g == 1) ? bi_ : (g == 2) ? bg_ : bo_;
        g_ball[idx] = bv[c];
    }
    if (idx < TT * 128) g_pf[idx] = 0u;
}

__global__ void convx_kernel(const float* __restrict__ inp) {
    int idx = blockIdx.x * 256 + threadIdx.x;   // s*1024 + k
    int s = idx >> 10, k = idx & 1023;
    float v = inp[idx];
    bf16 h = __float2bfloat16(v);
    g_X2[(size_t)s * KK2 + k]        = h;
    g_X2[(size_t)s * KK2 + 1024 + k] = __float2bfloat16(v - __bfloat162float(h));
}

// ================= xproj (round-15 verbatim) =================
#define X_P   136                      // smem pitch (bf16)
#define X_TB  (128 * X_P * 2)          // 34816 B per tile buffer
#define X_SMEM (4 * X_TB)              // A0,A1,B0,B1 = 139264

__device__ __forceinline__ void xp_issue(uint32_t sb, int tid, int ck, int m0, int n0) {
    uint32_t ab = sb + (uint32_t)(ck & 1) * X_TB;
    uint32_t bb = sb + 2 * X_TB + (uint32_t)(ck & 1) * X_TB;
    int ka = (ck < 16) ? ck * 128 : (ck - 16) * 128;   // A: hi, lo, hi
    int kb = (ck < 8) ? ck * 128 : (ck - 8) * 128;     // B: hi, hi, lo
#pragma unroll
    for (int it = 0; it < 8; ++it) {
        int j = tid + it * 256;
        int r = j >> 4, kq = j & 15;
        uint32_t off = (uint32_t)(r * X_P + kq * 8) * 2;
        cp16(ab + off, g_Wx2 + (size_t)(m0 + r) * KK2 + ka + kq * 8);
        cp16(bb + off, g_X2 + (size_t)(n0 + r) * KK2 + kb + kq * 8);
    }
    CP_COMMIT();
}

__global__ __launch_bounds__(256) void xproj_kernel() {
    extern __shared__ __align__(16) char smem[];
    uint32_t sb = smem_u32(smem);
    const int tid = threadIdx.x;
    const int w = tid >> 5, lane = tid & 31;
    const int g = lane >> 2, c4 = lane & 3;
    const int m0 = blockIdx.x * 128, n0 = blockIdx.y * 128;
    const int mg = w >> 1, ngp = w & 1;     // warp tile: m32 x n64
    const int lrow = lane & 15;
    const int lko  = (lane >> 4) * 8;

    float acc[2][8][4];
#pragma unroll
    for (int a = 0; a < 2; ++a)
#pragma unroll
        for (int b = 0; b < 8; ++b)
#pragma unroll
            for (int d = 0; d < 4; ++d) acc[a][b][d] = 0.f;

    xp_issue(sb, tid, 0, m0, n0);
    for (int ck = 0; ck < 24; ++ck) {
        if (ck < 23) { xp_issue(sb, tid, ck + 1, m0, n0); CP_WAIT1(); }
        else CP_WAIT0();
        __syncthreads();
        uint32_t ab = sb + (uint32_t)(ck & 1) * X_TB;
        uint32_t bb = sb + 2 * X_TB + (uint32_t)(ck & 1) * X_TB;
#pragma unroll
        for (int kk = 0; kk < 8; ++kk) {
            int kb = kk * 16 + lko;
            uint32_t af[2][4], bf_[4][4];
#pragma unroll
            for (int mt = 0; mt < 2; ++mt)
                ldm4(af[mt], ab + (uint32_t)((32 * mg + 16 * mt + lrow) * X_P + kb) * 2);
#pragma unroll
            for (int nt2 = 0; nt2 < 4; ++nt2)
                ldm4(bf_[nt2], bb + (uint32_t)((64 * ngp + 16 * nt2 + lrow) * X_P + kb) * 2);
#pragma unroll
            for (int nt2 = 0; nt2 < 4; ++nt2) {
#pragma unroll
                for (int hf2 = 0; hf2 < 2; ++hf2) {
                    uint32_t b0 = bf_[nt2][hf2], b1 = bf_[nt2][hf2 + 2];
#pragma unroll
                    for (int mt = 0; mt < 2; ++mt)
                        mma16816(acc[mt][2 * nt2 + hf2],
                                 af[mt][0], af[mt][1], af[mt][2], af[mt][3], b0, b1);
                }
            }
        }
        __syncthreads();
    }
#pragma unroll
    for (int mt = 0; mt < 2; ++mt) {
        int mrow = m0 + 32 * mg + 16 * mt + g;
        float bv0 = g_ball[mrow], bv1 = g_ball[mrow + 8];
#pragma unroll
        for (int nt = 0; nt < 8; ++nt) {
            int nrow = n0 + 64 * ngp + 8 * nt + 2 * c4;
            g_XW[(size_t)nrow * NG + mrow]           = acc[mt][nt][0] + bv0;
            g_XW[(size_t)(nrow + 1) * NG + mrow]     = acc[mt][nt][1] + bv0;
            g_XW[(size_t)nrow * NG + mrow + 8]       = acc[mt][nt][2] + bv1;
            g_XW[(size_t)(nrow + 1) * NG + mrow + 8] = acc[mt][nt][3] + bv1;
        }
    }
}

// ================= persistent recurrence: chunk flags + mg2/ngp2/kg4 retile =================
// 128 CTAs x 512 threads. CTA: M32 x N64, full W [hi|lo] resident in SMEM.
// Warp grid: mg(2) x ngp(2, n32 each) x kg(4, kk in {kg, kg+4} of every chunk).
// No global barrier: per-(t,group) produce flags; chunk ck consumes groups 2ck, 2ck+1.
#define R_PW  2056                     // W pitch (el): 4112B % 128 == 16 -> ldmatrix-safe
#define R_WB  (32 * R_PW * 2)          // 131584
#define R_P   136                      // h chunk pitch (el): 272B % 128 == 16
#define R_SPL (64 * R_P * 2)           // 17408 per split (hhi or hlo)
#define R_TB  (2 * R_SPL)              // 34816 per chunk buffer
#define R_DOF (R_WB + 2 * R_TB)        // 201216
#define R_DSZ (32 * 65 * 4)            // 8320 per D partial (2 buffers; kg2/3 merge into kg0/1)
#define R_SMEM (R_DOF + 2 * R_DSZ)     // 217856

__device__ __forceinline__ void recur_issueB(uint32_t sb, int tid, int ck, int par, int fbase) {
    // wait for the two producer groups of this chunk (step t-1 flags)
    volatile unsigned int* fp = g_pf + fbase + (2 * ck) * 8;
    while (fp[0] < 8u || fp[8] < 8u) { __nanosleep(32); }
    uint32_t base = sb + R_WB + (uint32_t)(ck & 1) * R_TB;
#pragma unroll
    for (int it = 0; it < 2; ++it) {
        int j = tid + it * 512;            // 1024 16B-units per split
        int n = j >> 4, kq = j & 15;
        uint32_t d = base + (uint32_t)(n * R_P + kq * 8) * 2;
        const bf16* s = g_h2[par] + (size_t)n * KK2 + ck * 128 + kq * 8;
        cp16(d,         s);                // hhi chunk
        cp16(d + R_SPL, s + 1024);         // hlo chunk
    }
    CP_COMMIT();
}

__device__ __forceinline__ float sigf(float x) { return 1.0f / (1.0f + __expf(-x)); }

__global__ __launch_bounds__(512) void recur_kernel(float* __restrict__ out) {
    extern __shared__ __align__(16) char smem[];
    uint32_t sb = smem_u32(smem);
    const int tid = threadIdx.x;
    const int w = tid >> 5, lane = tid & 31;
    const int g = lane >> 2, c4 = lane & 3;
    const int m0 = blockIdx.x * 32;     // gate-row base
    const int j0 = blockIdx.x * 8;      // hidden-unit base
    const int grp = blockIdx.x >> 3;    // producer group (16 groups of 8 CTAs)
    const int mg = w & 1;               // m16 tile
    const int ngp = (w >> 1) & 1;       // n32 tile
    const int kg = w >> 2;              // k-split quarter: kk in {kg, kg+4}
    const int lrow = lane & 15;
    const int lko  = (lane >> 4) * 8;

    // ---- load this CTA's W [hi|lo] slice into SMEM once ----
#pragma unroll
    for (int it = 0; it < 16; ++it) {
        int j = tid + it * 512;             // 0..8191 16B-units
        int r = j >> 8, kq = j & 255;
        uint32_t off = (uint32_t)(r * R_PW + kq * 8) * 2;
        uint4 v = *(const uint4*)(g_Wh2 + (size_t)(m0 + r) * KK2 + kq * 8);
        sts128(sb + off, v);
    }
    __syncthreads();

    // ---- t = 0 (h_{-1} = 0): 1 cell per thread, then set produce flag[0] ----
    float cc;
    const int cu = tid >> 6, cb = tid & 63;
    {
        float4 xw = *(const float4*)(g_XW + (size_t)cb * NG + m0 + 4 * cu);
        float i = sigf(xw.y), gg = tanhf(xw.z), o = sigf(xw.w);
        cc = i * gg;
        float h = o * tanhf(cc);
        out[(size_t)cb * HH + j0 + cu] = h;
        bf16 hh = __float2bfloat16(h);
        g_h2[0][cb * KK2 + j0 + cu]        = hh;
        g_h2[0][cb * KK2 + 1024 + j0 + cu] = __float2bfloat16(h - __bfloat162float(hh));
    }
    __threadfence();
    __syncthreads();
    if (tid == 0) atomicAdd(&g_pf[grp * 8], 1u);

    const uint32_t d0 = sb + R_DOF;
    const uint32_t dk = d0 + (uint32_t)(kg & 1) * R_DSZ;   // kg0/2 -> buf0, kg1/3 -> buf1
    const uint32_t abase = sb + (uint32_t)((16 * mg + lrow) * R_PW) * 2;
    for (int t = 1; t < TT; ++t) {
        const int rpar = (t - 1) & 1;
        const int wpar = t & 1;
        const int fbase = (t - 1) * 128;
        float acc[4][4];
#pragma unroll
        for (int j = 0; j < 4; ++j)
#pragma unroll
            for (int d = 0; d < 4; ++d) acc[j][d] = 0.f;
        recur_issueB(sb, tid, 0, rpar, fbase);
        // prefetch this step's xw off the post-GEMM critical path
        float4 xw = *(const float4*)(g_XW + (size_t)t * BG + (size_t)cb * NG + m0 + 4 * cu);
        for (int ck = 0; ck < 8; ++ck) {
            if (ck < 7) { recur_issueB(sb, tid, ck + 1, rpar, fbase); CP_WAIT1(); }
            else CP_WAIT0();
            __syncthreads();
            uint32_t bbase = sb + R_WB + (uint32_t)(ck & 1) * R_TB
                           + (uint32_t)((32 * ngp + lrow) * R_P) * 2;
            const int kc = ck * 128;
#pragma unroll
            for (int kq2 = 0; kq2 < 2; ++kq2) {
                const int kkl = kg + 4 * kq2;      // this warp's kk of the chunk
                uint32_t ah[4], al[4], bh0[4], bh1[4], bl0[4], bl1[4];
                uint32_t aoff = abase + (uint32_t)(kc + kkl * 16 + lko) * 2;
                ldm4(ah, aoff);                    // W hi (m16 x k16)
                ldm4(al, aoff + 1024 * 2);         // W lo
                uint32_t boff = bbase + (uint32_t)(kkl * 16 + lko) * 2;
                ldm4(bh0, boff);                   // h hi rows 0..15 of n32
                ldm4(bh1, boff + (uint32_t)(16 * R_P) * 2);   // h hi rows 16..31
                ldm4(bl0, boff + R_SPL);           // h lo rows 0..15
                ldm4(bl1, boff + R_SPL + (uint32_t)(16 * R_P) * 2);
#pragma unroll
                for (int j = 0; j < 4; ++j) {      // n8 tiles of this warp's n32
                    uint32_t* bhs = (j < 2) ? bh0 : bh1;
                    uint32_t* bls = (j < 2) ? bl0 : bl1;
                    uint32_t b0h = bhs[j & 1], b1h = bhs[(j & 1) + 2];
                    uint32_t b0l = bls[j & 1], b1l = bls[(j & 1) + 2];
                    mma16816(acc[j], ah[0], ah[1], ah[2], ah[3], b0h, b1h);
                    mma16816(acc[j], al[0], al[1], al[2], al[3], b0h, b1h);
                    mma16816(acc[j], ah[0], ah[1], ah[2], ah[3], b0l, b1l);
                }
            }
            __syncthreads();
        }
        // ---- stage D: kg 0,1 write; kg 2,3 add ----
        {
            int r = 16 * mg + g;
            if (kg < 2) {
#pragma unroll
                for (int j = 0; j < 4; ++j) {
                    int nb = 32 * ngp + 8 * j + 2 * c4;
                    sts_f32(dk + (uint32_t)(r * 65 + nb) * 4,           acc[j][0]);
                    sts_f32(dk + (uint32_t)(r * 65 + nb + 1) * 4,       acc[j][1]);
                    sts_f32(dk + (uint32_t)((r + 8) * 65 + nb) * 4,     acc[j][2]);
                    sts_f32(dk + (uint32_t)((r + 8) * 65 + nb + 1) * 4, acc[j][3]);
                }
            }
            __syncthreads();
            if (kg >= 2) {
#pragma unroll
                for (int j = 0; j < 4; ++j) {
                    int nb = 32 * ngp + 8 * j + 2 * c4;
                    uint32_t a00 = dk + (uint32_t)(r * 65 + nb) * 4;
                    uint32_t a01 = dk + (uint32_t)(r * 65 + nb + 1) * 4;
                    uint32_t a10 = dk + (uint32_t)((r + 8) * 65 + nb) * 4;
                    uint32_t a11 = dk + (uint32_t)((r + 8) * 65 + nb + 1) * 4;
                    sts_f32(a00, lds_f32(a00) + acc[j][0]);
                    sts_f32(a01, lds_f32(a01) + acc[j][1]);
                    sts_f32(a10, lds_f32(a10) + acc[j][2]);
                    sts_f32(a11, lds_f32(a11) + acc[j][3]);
                }
            }
            __syncthreads();
        }
        // ---- cell update: 1 cell per thread, sum the two partial buffers ----
        {
            float hf  = lds_f32(d0 + (uint32_t)((4 * cu + 0) * 65 + cb) * 4)
                      + lds_f32(d0 + R_DSZ + (uint32_t)((4 * cu + 0) * 65 + cb) * 4);
            float hi_ = lds_f32(d0 + (uint32_t)((4 * cu + 1) * 65 + cb) * 4)
                      + lds_f32(d0 + R_DSZ + (uint32_t)((4 * cu + 1) * 65 + cb) * 4);
            float hg  = lds_f32(d0 + (uint32_t)((4 * cu + 2) * 65 + cb) * 4)
                      + lds_f32(d0 + R_DSZ + (uint32_t)((4 * cu + 2) * 65 + cb) * 4);
            float ho  = lds_f32(d0 + (uint32_t)((4 * cu + 3) * 65 + cb) * 4)
                      + lds_f32(d0 + R_DSZ + (uint32_t)((4 * cu + 3) * 65 + cb) * 4);
            float f  = sigf(xw.x + hf);
            float i  = sigf(xw.y + hi_);
            float gg = tanhf(xw.z + hg);
            float o  = sigf(xw.w + ho);
            cc = f * cc + i * gg;
            float h = o * tanhf(cc);
            out[(size_t)t * BH + (size_t)cb * HH + j0 + cu] = h;
            bf16 hh = __float2bfloat16(h);
            g_h2[wpar][cb * KK2 + j0 + cu]        = hh;
            g_h2[wpar][cb * KK2 + 1024 + j0 + cu] = __float2bfloat16(h - __bfloat162float(hh));
            if (t == TT - 1) {
                out[(size_t)TT * BH + (size_t)cb * HH + j0 + cu] = h;          // hx
                out[(size_t)TT * BH + BH + (size_t)cb * HH + j0 + cu] = cc;    // cx
            }
        }
        // ---- publish this CTA's h_t (no global barrier) ----
        if (t < TT - 1) {
            __threadfence();
            __syncthreads();
            if (tid == 0) atomicAdd(&g_pf[t * 128 + grp * 8], 1u);
        }
    }
}

// ---------------- launch ----------------
extern "C" void kernel_launch(void* const* d_in, const int* in_sizes, int n_in,
                              void* d_out, int out_size) {
    const float* inputs = (const float*)d_in[0];
    const float* Wf = (const float*)d_in[1];
    const float* bf_ = (const float*)d_in[2];
    const float* Wi = (const float*)d_in[3];
    const float* bi_ = (const float*)d_in[4];
    const float* Wg = (const float*)d_in[5];
    const float* bg_ = (const float*)d_in[6];
    const float* Wo = (const float*)d_in[7];
    const float* bo_ = (const float*)d_in[8];
    float* out = (float*)d_out;
    (void)in_sizes; (void)n_in; (void)out_size;

    cudaFuncSetAttribute(xproj_kernel, cudaFuncAttributeMaxDynamicSharedMemorySize, X_SMEM);
    cudaFuncSetAttribute(recur_kernel, cudaFuncAttributeMaxDynamicSharedMemorySize, R_SMEM);

    // 1) repack (K-MAJOR convention) + zero produce flags
    repack_kernel<<<(KK * NG) / 256, 256>>>(Wf, Wi, Wg, Wo, bf_, bi_, bg_, bo_);

    // 2) split inputs into [hi|lo]
    convx_kernel<<<(TT * BB * KK) / 256, 256>>>(inputs);

    // 3) x-projections (round-15 verbatim)
    xproj_kernel<<<dim3(32, 256), 256, X_SMEM>>>();

    // 4) persistent recurrence: chunk-level producer flags, mg2/ngp2/kg4 retile
    recur_kernel<<<128, 512, R_SMEM>>>(out);
}